// round 7
// baseline (speedup 1.0000x reference)
#include <cuda_runtime.h>
#include <math.h>

#define N_MAX 1000000
#define PART_MAX 4096

// ---------------- device scratch (no allocation allowed) ----------------
static __device__ float    g_deg[N_MAX];     // weighted in-degree (zero at entry, re-zeroed post-use)
static __device__ float    g_dinv[N_MAX];    // rsqrt(deg)
static __device__ float4   g_x[N_MAX];       // x=emb@w_conv -> premult dinv*x -> conv1 out
static __device__ float4   g_agg[N_MAX];     // unnormalized message accumulator
static __device__ float    g_pmax[3 * PART_MAX]; // per-block column max
static __device__ float    g_psum[3 * PART_MAX]; // per-block sum exp(o - blockmax)
static __device__ float    g_lse[3];         // final logsumexp per column

// packed weights: [0:9) w_conv, [9:12) b_conv, [12:48) w1, [48:54) b1,
//                 [54:72) w3, [72:75) b3
static __device__ float g_w[80];

__device__ __forceinline__ float lrelu(float x) { return x >= 0.f ? x : 0.01f * x; }

__device__ __forceinline__ void red_v4(float* p, float a, float b, float c) {
    asm volatile("red.global.add.v4.f32 [%0], {%1, %2, %3, %4};"
                 :: "l"(p), "f"(a), "f"(b), "f"(c), "f"(0.f) : "memory");
}

// ---------------- kernels ----------------

__global__ void k_weights(const float* __restrict__ wconv, const float* __restrict__ bconv,
                          const float* __restrict__ w1, const float* __restrict__ b1,
                          const float* __restrict__ w3, const float* __restrict__ b3) {
    int t = threadIdx.x;
    if (t < 9)  g_w[t]      = wconv[t];
    if (t < 3)  g_w[9 + t]  = bconv[t];
    if (t < 36) g_w[12 + t] = w1[t];
    if (t < 6)  g_w[48 + t] = b1[t];
    if (t < 18) g_w[54 + t] = w3[t];
    if (t < 3)  g_w[72 + t] = b3[t];
}

// x = emb @ w_conv; zero agg   (side stream, overlaps k_deg)
__global__ void k_initx(const float* __restrict__ emb, int n) {
    int i = blockIdx.x * blockDim.x + threadIdx.x;
    if (i < n) {
        float e0 = emb[3 * i + 0];
        float e1 = emb[3 * i + 1];
        float e2 = emb[3 * i + 2];
        float4 x;
        x.x = e0 * g_w[0] + e1 * g_w[3] + e2 * g_w[6];
        x.y = e0 * g_w[1] + e1 * g_w[4] + e2 * g_w[7];
        x.z = e0 * g_w[2] + e1 * g_w[5] + e2 * g_w[8];
        x.w = 0.f;
        g_x[i] = x;
        g_agg[i] = make_float4(0.f, 0.f, 0.f, 0.f);
    }
}

// weighted in-degree over target nodes (col); 4 edges per thread
// PRECONDITION: g_deg == 0 (BSS-zero on first call; k_zerodeg restores per call)
__global__ void k_deg(const int4* __restrict__ col4, const float4* __restrict__ ew4,
                      int e4, const int* __restrict__ col, const float* __restrict__ ew, int e) {
    int i = blockIdx.x * blockDim.x + threadIdx.x;
    if (i < e4) {
        int4   c = __ldcs(&col4[i]);
        float4 w = __ldcs(&ew4[i]);
        atomicAdd(&g_deg[c.x], w.x);
        atomicAdd(&g_deg[c.y], w.y);
        atomicAdd(&g_deg[c.z], w.z);
        atomicAdd(&g_deg[c.w], w.w);
    }
    if (i == 0) {
        for (int j = e4 * 4; j < e; j++) atomicAdd(&g_deg[col[j]], ew[j]);
    }
}

// dinv = rsqrt(deg); premultiply x_pre = dinv * x   (4 nodes/thread, vectorized)
__global__ void k_dinv(int n4, int n) {
    int i = blockIdx.x * blockDim.x + threadIdx.x;
    if (i < n4) {
        float4 d = ((const float4*)g_deg)[i];
        float4 di;
        di.x = d.x > 0.f ? rsqrtf(d.x) : 0.f;
        di.y = d.y > 0.f ? rsqrtf(d.y) : 0.f;
        di.z = d.z > 0.f ? rsqrtf(d.z) : 0.f;
        di.w = d.w > 0.f ? rsqrtf(d.w) : 0.f;
        ((float4*)g_dinv)[i] = di;
        int b = i * 4;
        float4 x0 = g_x[b + 0];
        float4 x1 = g_x[b + 1];
        float4 x2 = g_x[b + 2];
        float4 x3 = g_x[b + 3];
        x0.x *= di.x; x0.y *= di.x; x0.z *= di.x;
        x1.x *= di.y; x1.y *= di.y; x1.z *= di.y;
        x2.x *= di.z; x2.y *= di.z; x2.z *= di.z;
        x3.x *= di.w; x3.y *= di.w; x3.z *= di.w;
        g_x[b + 0] = x0;
        g_x[b + 1] = x1;
        g_x[b + 2] = x2;
        g_x[b + 3] = x3;
    }
    if (i == 0) {
        for (int j = n4 * 4; j < n; j++) {
            float d = g_deg[j];
            float di = d > 0.f ? rsqrtf(d) : 0.f;
            g_dinv[j] = di;
            float4 x = g_x[j];
            x.x *= di; x.y *= di; x.z *= di;
            g_x[j] = x;
        }
    }
}

// re-zero deg for the next call/replay (side stream, overlaps k_msg)
__global__ void k_zerodeg(int n) {
    int i = blockIdx.x * blockDim.x + threadIdx.x;
    if (i < n) g_deg[i] = 0.f;
}

// agg[col] += ew * x_pre[row]   (2 random sectors per edge: gather + v4 red)
__global__ void k_msg(const int4* __restrict__ row4, const int4* __restrict__ col4,
                      const float4* __restrict__ ew4, int e4,
                      const int* __restrict__ row, const int* __restrict__ col,
                      const float* __restrict__ ew, int e) {
    int i = blockIdx.x * blockDim.x + threadIdx.x;
    if (i < e4) {
        int4   r = __ldcs(&row4[i]);
        int4   c = __ldcs(&col4[i]);
        float4 w = __ldcs(&ew4[i]);
        float4 x0 = g_x[r.x];
        float4 x1 = g_x[r.y];
        float4 x2 = g_x[r.z];
        float4 x3 = g_x[r.w];
        red_v4(reinterpret_cast<float*>(&g_agg[c.x]), w.x * x0.x, w.x * x0.y, w.x * x0.z);
        red_v4(reinterpret_cast<float*>(&g_agg[c.y]), w.y * x1.x, w.y * x1.y, w.y * x1.z);
        red_v4(reinterpret_cast<float*>(&g_agg[c.z]), w.z * x2.x, w.z * x2.y, w.z * x2.z);
        red_v4(reinterpret_cast<float*>(&g_agg[c.w]), w.w * x3.x, w.w * x3.y, w.w * x3.z);
    }
    if (i == 0) {
        for (int j = e4 * 4; j < e; j++) {
            float4 xv = g_x[row[j]];
            float  w  = ew[j];
            red_v4(reinterpret_cast<float*>(&g_agg[col[j]]), w * xv.x, w * xv.y, w * xv.z);
        }
    }
}

// conv1 output: x = leaky_relu(dinv[c]*agg[c] + b_conv)   (4 nodes/thread)
__global__ void k_node(int n4, int n) {
    int i = blockIdx.x * blockDim.x + threadIdx.x;
    float b0 = g_w[9], b1 = g_w[10], b2 = g_w[11];
    if (i < n4) {
        float4 di = ((const float4*)g_dinv)[i];
        int b = i * 4;
        float4 a0 = g_agg[b + 0];
        float4 a1 = g_agg[b + 1];
        float4 a2 = g_agg[b + 2];
        float4 a3 = g_agg[b + 3];
        g_x[b + 0] = make_float4(lrelu(di.x * a0.x + b0), lrelu(di.x * a0.y + b1), lrelu(di.x * a0.z + b2), 0.f);
        g_x[b + 1] = make_float4(lrelu(di.y * a1.x + b0), lrelu(di.y * a1.y + b1), lrelu(di.y * a1.z + b2), 0.f);
        g_x[b + 2] = make_float4(lrelu(di.z * a2.x + b0), lrelu(di.z * a2.y + b1), lrelu(di.z * a2.z + b2), 0.f);
        g_x[b + 3] = make_float4(lrelu(di.w * a3.x + b0), lrelu(di.w * a3.y + b1), lrelu(di.w * a3.z + b2), 0.f);
    }
    if (i == 0) {
        for (int j = n4 * 4; j < n; j++) {
            float4 a = g_agg[j];
            float di = g_dinv[j];
            g_x[j] = make_float4(lrelu(di * a.x + b0), lrelu(di * a.y + b1), lrelu(di * a.z + b2), 0.f);
        }
    }
}

// MLP per batch element; emits out + per-block (max, sum exp(o - max)) partials
// 8 items/thread; int4 index loads, float4 output stores
#define MLP_ITEMS 8
__global__ void k_mlp(const int4* __restrict__ home4, const int4* __restrict__ away4,
                      float4* __restrict__ out4, int b) {
    __shared__ float w[80];
    if (threadIdx.x < 80) w[threadIdx.x] = g_w[threadIdx.x];
    __syncthreads();

    int tid  = blockIdx.x * blockDim.x + threadIdx.x;
    int base = tid * MLP_ITEMS;            // item index; base*3 divisible by 4
    float o[MLP_ITEMS][3];
    int   nval = 0;
    float m0 = -INFINITY, m1 = -INFINITY, m2 = -INFINITY;

    if (base + MLP_ITEMS <= b) {
        int4 h0 = __ldg(&home4[tid * 2]);
        int4 h1 = __ldg(&home4[tid * 2 + 1]);
        int4 a0 = __ldg(&away4[tid * 2]);
        int4 a1 = __ldg(&away4[tid * 2 + 1]);
        int hi[8] = {h0.x, h0.y, h0.z, h0.w, h1.x, h1.y, h1.z, h1.w};
        int ai[8] = {a0.x, a0.y, a0.z, a0.w, a1.x, a1.y, a1.z, a1.w};
        #pragma unroll
        for (int t = 0; t < MLP_ITEMS; t++) {
            float4 xh = g_x[hi[t]];
            float4 xa = g_x[ai[t]];
            float h[6] = {xh.x, xh.y, xh.z, xa.x, xa.y, xa.z};
            float u[6];
            #pragma unroll
            for (int j = 0; j < 6; j++) {
                float s = w[48 + j];
                #pragma unroll
                for (int i2 = 0; i2 < 6; i2++) s += h[i2] * w[12 + i2 * 6 + j];
                u[j] = lrelu(s);
            }
            #pragma unroll
            for (int j = 0; j < 3; j++) {
                float s = w[72 + j];
                #pragma unroll
                for (int i2 = 0; i2 < 6; i2++) s += u[i2] * w[54 + i2 * 3 + j];
                o[t][j] = lrelu(s);
            }
            m0 = fmaxf(m0, o[t][0]);
            m1 = fmaxf(m1, o[t][1]);
            m2 = fmaxf(m2, o[t][2]);
        }
        nval = MLP_ITEMS;
        // 24 contiguous floats -> 6 float4 stores
        const float* of = &o[0][0];
        int vbase = (base * 3) / 4;
        #pragma unroll
        for (int v = 0; v < 6; v++)
            out4[vbase + v] = make_float4(of[4 * v], of[4 * v + 1], of[4 * v + 2], of[4 * v + 3]);
    } else {
        // tail: scalar path
        const int* home = (const int*)home4;
        const int* away = (const int*)away4;
        float* out = (float*)out4;
        #pragma unroll
        for (int t = 0; t < MLP_ITEMS; t++) {
            int idx = base + t;
            if (idx < b) {
                float4 xh = g_x[__ldg(&home[idx])];
                float4 xa = g_x[__ldg(&away[idx])];
                float h[6] = {xh.x, xh.y, xh.z, xa.x, xa.y, xa.z};
                float u[6];
                #pragma unroll
                for (int j = 0; j < 6; j++) {
                    float s = w[48 + j];
                    #pragma unroll
                    for (int i2 = 0; i2 < 6; i2++) s += h[i2] * w[12 + i2 * 6 + j];
                    u[j] = lrelu(s);
                }
                #pragma unroll
                for (int j = 0; j < 3; j++) {
                    float s = w[72 + j];
                    #pragma unroll
                    for (int i2 = 0; i2 < 6; i2++) s += u[i2] * w[54 + i2 * 3 + j];
                    o[t][j] = lrelu(s);
                }
                out[3 * idx + 0] = o[t][0];
                out[3 * idx + 1] = o[t][1];
                out[3 * idx + 2] = o[t][2];
                m0 = fmaxf(m0, o[t][0]);
                m1 = fmaxf(m1, o[t][1]);
                m2 = fmaxf(m2, o[t][2]);
                nval = t + 1;
            }
        }
    }

    // block max reduction
    #pragma unroll
    for (int off = 16; off; off >>= 1) {
        m0 = fmaxf(m0, __shfl_xor_sync(0xFFFFFFFFu, m0, off));
        m1 = fmaxf(m1, __shfl_xor_sync(0xFFFFFFFFu, m1, off));
        m2 = fmaxf(m2, __shfl_xor_sync(0xFFFFFFFFu, m2, off));
    }
    __shared__ float sm[3][8];
    int lane = threadIdx.x & 31, wpw = threadIdx.x >> 5;
    if (lane == 0) { sm[0][wpw] = m0; sm[1][wpw] = m1; sm[2][wpw] = m2; }
    __syncthreads();
    float M0 = sm[0][0], M1 = sm[1][0], M2 = sm[2][0];
    #pragma unroll
    for (int k = 1; k < 8; k++) {
        M0 = fmaxf(M0, sm[0][k]); M1 = fmaxf(M1, sm[1][k]); M2 = fmaxf(M2, sm[2][k]);
    }
    // block sums of exp(o - blockmax) from registers
    float s0 = 0.f, s1 = 0.f, s2 = 0.f;
    #pragma unroll
    for (int t = 0; t < MLP_ITEMS; t++) {
        if (t < nval) {
            s0 += __expf(o[t][0] - M0);
            s1 += __expf(o[t][1] - M1);
            s2 += __expf(o[t][2] - M2);
        }
    }
    #pragma unroll
    for (int off = 16; off; off >>= 1) {
        s0 += __shfl_xor_sync(0xFFFFFFFFu, s0, off);
        s1 += __shfl_xor_sync(0xFFFFFFFFu, s1, off);
        s2 += __shfl_xor_sync(0xFFFFFFFFu, s2, off);
    }
    __syncthreads();
    if (lane == 0) { sm[0][wpw] = s0; sm[1][wpw] = s1; sm[2][wpw] = s2; }
    __syncthreads();
    if (threadIdx.x == 0) {
        float t0 = 0.f, t1 = 0.f, t2 = 0.f;
        #pragma unroll
        for (int k = 0; k < 8; k++) { t0 += sm[0][k]; t1 += sm[1][k]; t2 += sm[2][k]; }
        int bb = blockIdx.x;
        g_pmax[0 * PART_MAX + bb] = M0;
        g_pmax[1 * PART_MAX + bb] = M1;
        g_pmax[2 * PART_MAX + bb] = M2;
        g_psum[0 * PART_MAX + bb] = t0;
        g_psum[1 * PART_MAX + bb] = t1;
        g_psum[2 * PART_MAX + bb] = t2;
    }
}

// merge per-block partials -> lse per column (single block)
__global__ void k_merge(int nb) {
    __shared__ float sred[32];
    int t = threadIdx.x;          // 1024 threads
    int lane = t & 31, wpw = t >> 5;
    for (int c = 0; c < 3; c++) {
        float m = (t < nb) ? g_pmax[c * PART_MAX + t] : -INFINITY;
        float mw = m;
        #pragma unroll
        for (int off = 16; off; off >>= 1) mw = fmaxf(mw, __shfl_xor_sync(0xFFFFFFFFu, mw, off));
        if (lane == 0) sred[wpw] = mw;
        __syncthreads();
        float M = sred[0];
        #pragma unroll
        for (int k = 1; k < 32; k++) M = fmaxf(M, sred[k]);
        __syncthreads();
        float s = (t < nb) ? g_psum[c * PART_MAX + t] * __expf(m - M) : 0.f;
        #pragma unroll
        for (int off = 16; off; off >>= 1) s += __shfl_xor_sync(0xFFFFFFFFu, s, off);
        if (lane == 0) sred[wpw] = s;
        __syncthreads();
        if (t == 0) {
            float S = 0.f;
            #pragma unroll
            for (int k = 0; k < 32; k++) S += sred[k];
            g_lse[c] = M + logf(S);
        }
        __syncthreads();
    }
}

// out -= lse[col]; 8 elems/thread (2x float4) + scalar tail
__global__ void k_final(float4* __restrict__ out4, int nvec2, float* __restrict__ out, int total) {
    float l0 = g_lse[0], l1 = g_lse[1], l2 = g_lse[2];
    int v = blockIdx.x * blockDim.x + threadIdx.x;   // pair index
    if (v < nvec2) {
        float4 oa = out4[2 * v];
        float4 ob = out4[2 * v + 1];
        int m = (v * 8) % 3;           // channel of first element
        float A, Bc, C;
        if (m == 0)      { A = l0; Bc = l1; C = l2; }
        else if (m == 1) { A = l1; Bc = l2; C = l0; }
        else             { A = l2; Bc = l0; C = l1; }
        oa.x -= A;  oa.y -= Bc; oa.z -= C;  oa.w -= A;
        ob.x -= Bc; ob.y -= C;  ob.z -= A;  ob.w -= Bc;
        out4[2 * v]     = oa;
        out4[2 * v + 1] = ob;
    }
    if (v == 0) {
        for (int j = nvec2 * 8; j < total; j++) out[j] -= g_lse[j % 3];
    }
}

// ---------------- launch ----------------
extern "C" void kernel_launch(void* const* d_in, const int* in_sizes, int n_in,
                              void* d_out, int out_size) {
    const int*   edge_index = (const int*)d_in[0];   // [2, E]
    const float* ew         = (const float*)d_in[1]; // [E]
    const int*   home       = (const int*)d_in[2];   // [B]
    const int*   away       = (const int*)d_in[3];   // [B]
    const float* emb        = (const float*)d_in[4]; // [N, 3]
    float*       out        = (float*)d_out;         // [B, 3]

    const int E = in_sizes[1];
    const int B = in_sizes[2];
    int       N = in_sizes[4] / 3;
    if (N > N_MAX) N = N_MAX;

    const int* row = edge_index;
    const int* col = edge_index + E;
    const int  E4  = E / 4;
    const int  N4  = N / 4;

    cudaStream_t s1;
    cudaStreamCreateWithFlags(&s1, cudaStreamNonBlocking);
    cudaEvent_t eFork, eJoin, eFork2, eJoin2;
    cudaEventCreateWithFlags(&eFork, cudaEventDisableTiming);
    cudaEventCreateWithFlags(&eJoin, cudaEventDisableTiming);
    cudaEventCreateWithFlags(&eFork2, cudaEventDisableTiming);
    cudaEventCreateWithFlags(&eJoin2, cudaEventDisableTiming);

    const int T = 256;

    // fork immediately: side does weights + x/agg init while main does deg atomics
    cudaEventRecord(eFork, 0);
    cudaStreamWaitEvent(s1, eFork, 0);
    k_weights<<<1, 64, 0, s1>>>((const float*)d_in[5], (const float*)d_in[6],
                                (const float*)d_in[7], (const float*)d_in[8],
                                (const float*)d_in[9], (const float*)d_in[10]);
    k_initx<<<(N + T - 1) / T, T, 0, s1>>>(emb, N);
    cudaEventRecord(eJoin, s1);

    // main: deg atomics start at t=0 (g_deg==0 invariant)
    k_deg<<<(E4 + T - 1) / T, T>>>((const int4*)col, (const float4*)ew, E4, col, ew, E);

    cudaStreamWaitEvent(0, eJoin, 0);   // join side work

    k_dinv<<<(N4 + T - 1) / T, T>>>(N4, N);

    // side: re-zero deg for next call, overlapped under k_msg
    cudaEventRecord(eFork2, 0);
    cudaStreamWaitEvent(s1, eFork2, 0);
    k_zerodeg<<<(N + T - 1) / T, T, 0, s1>>>(N);
    cudaEventRecord(eJoin2, s1);

    k_msg<<<(E4 + T - 1) / T, T>>>((const int4*)row, (const int4*)col,
                                   (const float4*)ew, E4, row, col, ew, E);
    k_node<<<(N4 + T - 1) / T, T>>>(N4, N);

    const int items_per_block = T * MLP_ITEMS;
    const int nb = (B + items_per_block - 1) / items_per_block;
    k_mlp<<<nb, T>>>((const int4*)home, (const int4*)away, (float4*)out, B);
    k_merge<<<1, 1024>>>(nb);

    cudaStreamWaitEvent(0, eJoin2, 0);  // join deg re-zero before graph end

    const int total = 3 * B;
    const int nvec2 = total / 8;
    k_final<<<(nvec2 + T - 1) / T, T>>>((float4*)out, nvec2, out, total);
}

// round 8
// speedup vs baseline: 1.0101x; 1.0101x over previous
#include <cuda_runtime.h>
#include <math.h>

#define N_MAX 1000000
#define PART_MAX 4096

// ---------------- device scratch (no allocation allowed) ----------------
static __device__ float    g_deg[N_MAX];     // weighted in-degree (zero at entry, re-zeroed post-use)
static __device__ float    g_dinv[N_MAX];    // rsqrt(deg)
static __device__ float4   g_x[N_MAX];       // x=emb@w_conv -> premult dinv*x -> conv1 out
static __device__ float4   g_agg[N_MAX];     // unnormalized message accumulator
static __device__ float    g_pmax[3 * PART_MAX]; // per-block column max
static __device__ float    g_psum[3 * PART_MAX]; // per-block sum exp(o - blockmax)
static __device__ float    g_lse[3];         // final logsumexp per column

// packed weights: [0:9) w_conv, [9:12) b_conv, [12:48) w1, [48:54) b1,
//                 [54:72) w3, [72:75) b3
static __device__ float g_w[80];

__device__ __forceinline__ float lrelu(float x) { return x >= 0.f ? x : 0.01f * x; }

__device__ __forceinline__ void red_v4(float* p, float a, float b, float c) {
    asm volatile("red.global.add.v4.f32 [%0], {%1, %2, %3, %4};"
                 :: "l"(p), "f"(a), "f"(b), "f"(c), "f"(0.f) : "memory");
}

// ---------------- kernels ----------------

__global__ void k_weights(const float* __restrict__ wconv, const float* __restrict__ bconv,
                          const float* __restrict__ w1, const float* __restrict__ b1,
                          const float* __restrict__ w3, const float* __restrict__ b3) {
    int t = threadIdx.x;
    if (t < 9)  g_w[t]      = wconv[t];
    if (t < 3)  g_w[9 + t]  = bconv[t];
    if (t < 36) g_w[12 + t] = w1[t];
    if (t < 6)  g_w[48 + t] = b1[t];
    if (t < 18) g_w[54 + t] = w3[t];
    if (t < 3)  g_w[72 + t] = b3[t];
}

// x = emb @ w_conv; zero agg   (side stream, overlaps k_deg)
__global__ void k_initx(const float* __restrict__ emb, int n) {
    int i = blockIdx.x * blockDim.x + threadIdx.x;
    if (i < n) {
        float e0 = emb[3 * i + 0];
        float e1 = emb[3 * i + 1];
        float e2 = emb[3 * i + 2];
        float4 x;
        x.x = e0 * g_w[0] + e1 * g_w[3] + e2 * g_w[6];
        x.y = e0 * g_w[1] + e1 * g_w[4] + e2 * g_w[7];
        x.z = e0 * g_w[2] + e1 * g_w[5] + e2 * g_w[8];
        x.w = 0.f;
        g_x[i] = x;
        g_agg[i] = make_float4(0.f, 0.f, 0.f, 0.f);
    }
}

// weighted in-degree over target nodes (col); 4 edges per thread
// PRECONDITION: g_deg == 0 (BSS-zero on first call; k_zerodeg restores per call)
__global__ void k_deg(const int4* __restrict__ col4, const float4* __restrict__ ew4,
                      int e4, const int* __restrict__ col, const float* __restrict__ ew, int e) {
    int i = blockIdx.x * blockDim.x + threadIdx.x;
    if (i < e4) {
        int4   c = __ldg(&col4[i]);
        float4 w = __ldg(&ew4[i]);
        atomicAdd(&g_deg[c.x], w.x);
        atomicAdd(&g_deg[c.y], w.y);
        atomicAdd(&g_deg[c.z], w.z);
        atomicAdd(&g_deg[c.w], w.w);
    }
    if (i == 0) {
        for (int j = e4 * 4; j < e; j++) atomicAdd(&g_deg[col[j]], ew[j]);
    }
}

// dinv = rsqrt(deg); premultiply x_pre = dinv * x
__global__ void k_dinv(int n) {
    int i = blockIdx.x * blockDim.x + threadIdx.x;
    if (i < n) {
        float d = g_deg[i];
        float di = d > 0.f ? rsqrtf(d) : 0.f;
        g_dinv[i] = di;
        float4 x = g_x[i];
        x.x *= di; x.y *= di; x.z *= di;
        g_x[i] = x;
    }
}

// re-zero deg for the next call/replay (side stream, overlaps k_msg)
__global__ void k_zerodeg(int n) {
    int i = blockIdx.x * blockDim.x + threadIdx.x;
    if (i < n) g_deg[i] = 0.f;
}

// agg[col] += ew * x_pre[row]   (2 random sectors per edge: gather + v4 red)
__global__ void k_msg(const int4* __restrict__ row4, const int4* __restrict__ col4,
                      const float4* __restrict__ ew4, int e4,
                      const int* __restrict__ row, const int* __restrict__ col,
                      const float* __restrict__ ew, int e) {
    int i = blockIdx.x * blockDim.x + threadIdx.x;
    if (i < e4) {
        int4   r = __ldg(&row4[i]);
        int4   c = __ldg(&col4[i]);
        float4 w = __ldg(&ew4[i]);
        float4 x0 = g_x[r.x];
        float4 x1 = g_x[r.y];
        float4 x2 = g_x[r.z];
        float4 x3 = g_x[r.w];
        red_v4(reinterpret_cast<float*>(&g_agg[c.x]), w.x * x0.x, w.x * x0.y, w.x * x0.z);
        red_v4(reinterpret_cast<float*>(&g_agg[c.y]), w.y * x1.x, w.y * x1.y, w.y * x1.z);
        red_v4(reinterpret_cast<float*>(&g_agg[c.z]), w.z * x2.x, w.z * x2.y, w.z * x2.z);
        red_v4(reinterpret_cast<float*>(&g_agg[c.w]), w.w * x3.x, w.w * x3.y, w.w * x3.z);
    }
    if (i == 0) {
        for (int j = e4 * 4; j < e; j++) {
            float4 xv = g_x[row[j]];
            float  w  = ew[j];
            red_v4(reinterpret_cast<float*>(&g_agg[col[j]]), w * xv.x, w * xv.y, w * xv.z);
        }
    }
}

// conv1 output: x = leaky_relu(dinv[c]*agg[c] + b_conv)
__global__ void k_node(int n) {
    int i = blockIdx.x * blockDim.x + threadIdx.x;
    if (i < n) {
        float4 a = g_agg[i];
        float  di = g_dinv[i];
        float4 o;
        o.x = lrelu(di * a.x + g_w[9]);
        o.y = lrelu(di * a.y + g_w[10]);
        o.z = lrelu(di * a.z + g_w[11]);
        o.w = 0.f;
        g_x[i] = o;
    }
}

// MLP per batch element; emits out + per-block (max, sum exp(o - max)) partials
// 8 items/thread; int4 index loads, float4 output stores
#define MLP_ITEMS 8
__global__ void k_mlp(const int4* __restrict__ home4, const int4* __restrict__ away4,
                      float4* __restrict__ out4, int b) {
    __shared__ float w[80];
    if (threadIdx.x < 80) w[threadIdx.x] = g_w[threadIdx.x];
    __syncthreads();

    int tid  = blockIdx.x * blockDim.x + threadIdx.x;
    int base = tid * MLP_ITEMS;            // item index; base*3 divisible by 4
    float o[MLP_ITEMS][3];
    int   nval = 0;
    float m0 = -INFINITY, m1 = -INFINITY, m2 = -INFINITY;

    if (base + MLP_ITEMS <= b) {
        int4 h0 = __ldg(&home4[tid * 2]);
        int4 h1 = __ldg(&home4[tid * 2 + 1]);
        int4 a0 = __ldg(&away4[tid * 2]);
        int4 a1 = __ldg(&away4[tid * 2 + 1]);
        int hi[8] = {h0.x, h0.y, h0.z, h0.w, h1.x, h1.y, h1.z, h1.w};
        int ai[8] = {a0.x, a0.y, a0.z, a0.w, a1.x, a1.y, a1.z, a1.w};
        #pragma unroll
        for (int t = 0; t < MLP_ITEMS; t++) {
            float4 xh = g_x[hi[t]];
            float4 xa = g_x[ai[t]];
            float h[6] = {xh.x, xh.y, xh.z, xa.x, xa.y, xa.z};
            float u[6];
            #pragma unroll
            for (int j = 0; j < 6; j++) {
                float s = w[48 + j];
                #pragma unroll
                for (int i2 = 0; i2 < 6; i2++) s += h[i2] * w[12 + i2 * 6 + j];
                u[j] = lrelu(s);
            }
            #pragma unroll
            for (int j = 0; j < 3; j++) {
                float s = w[72 + j];
                #pragma unroll
                for (int i2 = 0; i2 < 6; i2++) s += u[i2] * w[54 + i2 * 3 + j];
                o[t][j] = lrelu(s);
            }
            m0 = fmaxf(m0, o[t][0]);
            m1 = fmaxf(m1, o[t][1]);
            m2 = fmaxf(m2, o[t][2]);
        }
        nval = MLP_ITEMS;
        // 24 contiguous floats -> 6 float4 stores
        const float* of = &o[0][0];
        int vbase = (base * 3) / 4;
        #pragma unroll
        for (int v = 0; v < 6; v++)
            out4[vbase + v] = make_float4(of[4 * v], of[4 * v + 1], of[4 * v + 2], of[4 * v + 3]);
    } else {
        // tail: scalar path
        const int* home = (const int*)home4;
        const int* away = (const int*)away4;
        float* out = (float*)out4;
        #pragma unroll
        for (int t = 0; t < MLP_ITEMS; t++) {
            int idx = base + t;
            if (idx < b) {
                float4 xh = g_x[__ldg(&home[idx])];
                float4 xa = g_x[__ldg(&away[idx])];
                float h[6] = {xh.x, xh.y, xh.z, xa.x, xa.y, xa.z};
                float u[6];
                #pragma unroll
                for (int j = 0; j < 6; j++) {
                    float s = w[48 + j];
                    #pragma unroll
                    for (int i2 = 0; i2 < 6; i2++) s += h[i2] * w[12 + i2 * 6 + j];
                    u[j] = lrelu(s);
                }
                #pragma unroll
                for (int j = 0; j < 3; j++) {
                    float s = w[72 + j];
                    #pragma unroll
                    for (int i2 = 0; i2 < 6; i2++) s += u[i2] * w[54 + i2 * 3 + j];
                    o[t][j] = lrelu(s);
                }
                out[3 * idx + 0] = o[t][0];
                out[3 * idx + 1] = o[t][1];
                out[3 * idx + 2] = o[t][2];
                m0 = fmaxf(m0, o[t][0]);
                m1 = fmaxf(m1, o[t][1]);
                m2 = fmaxf(m2, o[t][2]);
                nval = t + 1;
            }
        }
    }

    // block max reduction
    #pragma unroll
    for (int off = 16; off; off >>= 1) {
        m0 = fmaxf(m0, __shfl_xor_sync(0xFFFFFFFFu, m0, off));
        m1 = fmaxf(m1, __shfl_xor_sync(0xFFFFFFFFu, m1, off));
        m2 = fmaxf(m2, __shfl_xor_sync(0xFFFFFFFFu, m2, off));
    }
    __shared__ float sm[3][8];
    int lane = threadIdx.x & 31, wpw = threadIdx.x >> 5;
    if (lane == 0) { sm[0][wpw] = m0; sm[1][wpw] = m1; sm[2][wpw] = m2; }
    __syncthreads();
    float M0 = sm[0][0], M1 = sm[1][0], M2 = sm[2][0];
    #pragma unroll
    for (int k = 1; k < 8; k++) {
        M0 = fmaxf(M0, sm[0][k]); M1 = fmaxf(M1, sm[1][k]); M2 = fmaxf(M2, sm[2][k]);
    }
    // block sums of exp(o - blockmax) from registers
    float s0 = 0.f, s1 = 0.f, s2 = 0.f;
    #pragma unroll
    for (int t = 0; t < MLP_ITEMS; t++) {
        if (t < nval) {
            s0 += __expf(o[t][0] - M0);
            s1 += __expf(o[t][1] - M1);
            s2 += __expf(o[t][2] - M2);
        }
    }
    #pragma unroll
    for (int off = 16; off; off >>= 1) {
        s0 += __shfl_xor_sync(0xFFFFFFFFu, s0, off);
        s1 += __shfl_xor_sync(0xFFFFFFFFu, s1, off);
        s2 += __shfl_xor_sync(0xFFFFFFFFu, s2, off);
    }
    __syncthreads();
    if (lane == 0) { sm[0][wpw] = s0; sm[1][wpw] = s1; sm[2][wpw] = s2; }
    __syncthreads();
    if (threadIdx.x == 0) {
        float t0 = 0.f, t1 = 0.f, t2 = 0.f;
        #pragma unroll
        for (int k = 0; k < 8; k++) { t0 += sm[0][k]; t1 += sm[1][k]; t2 += sm[2][k]; }
        int bb = blockIdx.x;
        g_pmax[0 * PART_MAX + bb] = M0;
        g_pmax[1 * PART_MAX + bb] = M1;
        g_pmax[2 * PART_MAX + bb] = M2;
        g_psum[0 * PART_MAX + bb] = t0;
        g_psum[1 * PART_MAX + bb] = t1;
        g_psum[2 * PART_MAX + bb] = t2;
    }
}

// merge per-block partials -> lse per column (single block)
__global__ void k_merge(int nb) {
    __shared__ float sred[32];
    int t = threadIdx.x;          // 1024 threads
    int lane = t & 31, wpw = t >> 5;
    for (int c = 0; c < 3; c++) {
        float m = (t < nb) ? g_pmax[c * PART_MAX + t] : -INFINITY;
        float mw = m;
        #pragma unroll
        for (int off = 16; off; off >>= 1) mw = fmaxf(mw, __shfl_xor_sync(0xFFFFFFFFu, mw, off));
        if (lane == 0) sred[wpw] = mw;
        __syncthreads();
        float M = sred[0];
        #pragma unroll
        for (int k = 1; k < 32; k++) M = fmaxf(M, sred[k]);
        __syncthreads();
        float s = (t < nb) ? g_psum[c * PART_MAX + t] * __expf(m - M) : 0.f;
        #pragma unroll
        for (int off = 16; off; off >>= 1) s += __shfl_xor_sync(0xFFFFFFFFu, s, off);
        if (lane == 0) sred[wpw] = s;
        __syncthreads();
        if (t == 0) {
            float S = 0.f;
            #pragma unroll
            for (int k = 0; k < 32; k++) S += sred[k];
            g_lse[c] = M + logf(S);
        }
        __syncthreads();
    }
}

// out -= lse[col]; 8 elems/thread (2x float4) + scalar tail
__global__ void k_final(float4* __restrict__ out4, int nvec2, float* __restrict__ out, int total) {
    float l0 = g_lse[0], l1 = g_lse[1], l2 = g_lse[2];
    int v = blockIdx.x * blockDim.x + threadIdx.x;   // pair index
    if (v < nvec2) {
        float4 oa = out4[2 * v];
        float4 ob = out4[2 * v + 1];
        int m = (v * 8) % 3;           // channel of first element
        float A, Bc, C;
        if (m == 0)      { A = l0; Bc = l1; C = l2; }
        else if (m == 1) { A = l1; Bc = l2; C = l0; }
        else             { A = l2; Bc = l0; C = l1; }
        oa.x -= A;  oa.y -= Bc; oa.z -= C;  oa.w -= A;
        ob.x -= Bc; ob.y -= C;  ob.z -= A;  ob.w -= Bc;
        out4[2 * v]     = oa;
        out4[2 * v + 1] = ob;
    }
    if (v == 0) {
        for (int j = nvec2 * 8; j < total; j++) out[j] -= g_lse[j % 3];
    }
}

// ---------------- launch ----------------
extern "C" void kernel_launch(void* const* d_in, const int* in_sizes, int n_in,
                              void* d_out, int out_size) {
    const int*   edge_index = (const int*)d_in[0];   // [2, E]
    const float* ew         = (const float*)d_in[1]; // [E]
    const int*   home       = (const int*)d_in[2];   // [B]
    const int*   away       = (const int*)d_in[3];   // [B]
    const float* emb        = (const float*)d_in[4]; // [N, 3]
    float*       out        = (float*)d_out;         // [B, 3]

    const int E = in_sizes[1];
    const int B = in_sizes[2];
    int       N = in_sizes[4] / 3;
    if (N > N_MAX) N = N_MAX;

    const int* row = edge_index;
    const int* col = edge_index + E;
    const int  E4  = E / 4;

    cudaStream_t s1;
    cudaStreamCreateWithFlags(&s1, cudaStreamNonBlocking);
    cudaEvent_t eFork, eJoin, eFork2, eJoin2;
    cudaEventCreateWithFlags(&eFork, cudaEventDisableTiming);
    cudaEventCreateWithFlags(&eJoin, cudaEventDisableTiming);
    cudaEventCreateWithFlags(&eFork2, cudaEventDisableTiming);
    cudaEventCreateWithFlags(&eJoin2, cudaEventDisableTiming);

    const int T = 256;

    // fork immediately: side does weights + x/agg init while main does deg atomics
    cudaEventRecord(eFork, 0);
    cudaStreamWaitEvent(s1, eFork, 0);
    k_weights<<<1, 64, 0, s1>>>((const float*)d_in[5], (const float*)d_in[6],
                                (const float*)d_in[7], (const float*)d_in[8],
                                (const float*)d_in[9], (const float*)d_in[10]);
    k_initx<<<(N + T - 1) / T, T, 0, s1>>>(emb, N);
    cudaEventRecord(eJoin, s1);

    // main: deg atomics start at t=0 (g_deg==0 invariant)
    k_deg<<<(E4 + T - 1) / T, T>>>((const int4*)col, (const float4*)ew, E4, col, ew, E);

    cudaStreamWaitEvent(0, eJoin, 0);   // join side work

    k_dinv<<<(N + T - 1) / T, T>>>(N);

    // side: re-zero deg for next call, overlapped under k_msg
    cudaEventRecord(eFork2, 0);
    cudaStreamWaitEvent(s1, eFork2, 0);
    k_zerodeg<<<(N + T - 1) / T, T, 0, s1>>>(N);
    cudaEventRecord(eJoin2, s1);

    k_msg<<<(E4 + T - 1) / T, T>>>((const int4*)row, (const int4*)col,
                                   (const float4*)ew, E4, row, col, ew, E);
    k_node<<<(N + T - 1) / T, T>>>(N);

    const int items_per_block = T * MLP_ITEMS;
    const int nb = (B + items_per_block - 1) / items_per_block;
    k_mlp<<<nb, T>>>((const int4*)home, (const int4*)away, (float4*)out, B);
    k_merge<<<1, 1024>>>(nb);

    cudaStreamWaitEvent(0, eJoin2, 0);  // join deg re-zero before graph end

    const int total = 3 * B;
    const int nvec2 = total / 8;
    k_final<<<(nvec2 + T - 1) / T, T>>>((float4*)out, nvec2, out, total);
}

// round 11
// speedup vs baseline: 1.0245x; 1.0142x over previous
#include <cuda_runtime.h>
#include <math.h>

#define N_MAX 1000000
#define PART_MAX 4096

// ---------------- device scratch (no allocation allowed) ----------------
static __device__ float    g_deg[N_MAX];     // weighted in-degree (zero at entry, re-zeroed post-use)
static __device__ float    g_dinv[N_MAX];    // rsqrt(deg)
static __device__ float4   g_x[N_MAX];       // x=emb@w_conv -> premult dinv*x -> conv1 out
static __device__ float4   g_agg[N_MAX];     // unnormalized message accumulator
static __device__ float    g_pmax[3 * PART_MAX]; // per-block column max
static __device__ float    g_psum[3 * PART_MAX]; // per-block sum exp(o - blockmax)
static __device__ float    g_lse[3];         // final logsumexp per column
static __device__ int      g_sink[2048];     // prefetch sink (never read)

// packed weights: [0:9) w_conv, [9:12) b_conv, [12:48) w1, [48:54) b1,
//                 [54:72) w3, [72:75) b3
static __device__ float g_w[80];

__device__ __forceinline__ float lrelu(float x) { return x >= 0.f ? x : 0.01f * x; }

__device__ __forceinline__ void red_v4(float* p, float a, float b, float c) {
    asm volatile("red.global.add.v4.f32 [%0], {%1, %2, %3, %4};"
                 :: "l"(p), "f"(a), "f"(b), "f"(c), "f"(0.f) : "memory");
}

// ---------------- kernels ----------------

__global__ void k_weights(const float* __restrict__ wconv, const float* __restrict__ bconv,
                          const float* __restrict__ w1, const float* __restrict__ b1,
                          const float* __restrict__ w3, const float* __restrict__ b3) {
    int t = threadIdx.x;
    if (t < 9)  g_w[t]      = wconv[t];
    if (t < 3)  g_w[9 + t]  = bconv[t];
    if (t < 36) g_w[12 + t] = w1[t];
    if (t < 6)  g_w[48 + t] = b1[t];
    if (t < 18) g_w[54 + t] = w3[t];
    if (t < 3)  g_w[72 + t] = b3[t];
}

// x = emb @ w_conv; zero agg   (side stream, overlaps k_deg)
__global__ void k_initx(const float* __restrict__ emb, int n) {
    int i = blockIdx.x * blockDim.x + threadIdx.x;
    if (i < n) {
        float e0 = emb[3 * i + 0];
        float e1 = emb[3 * i + 1];
        float e2 = emb[3 * i + 2];
        float4 x;
        x.x = e0 * g_w[0] + e1 * g_w[3] + e2 * g_w[6];
        x.y = e0 * g_w[1] + e1 * g_w[4] + e2 * g_w[7];
        x.z = e0 * g_w[2] + e1 * g_w[5] + e2 * g_w[8];
        x.w = 0.f;
        g_x[i] = x;
        g_agg[i] = make_float4(0.f, 0.f, 0.f, 0.f);
    }
}

// weighted in-degree over target nodes (col); 4 edges per thread
// PRECONDITION: g_deg == 0 (BSS-zero on first call; k_zeropre restores per call)
__global__ void k_deg(const int4* __restrict__ col4, const float4* __restrict__ ew4,
                      int e4, const int* __restrict__ col, const float* __restrict__ ew, int e) {
    int i = blockIdx.x * blockDim.x + threadIdx.x;
    if (i < e4) {
        int4   c = __ldg(&col4[i]);
        float4 w = __ldg(&ew4[i]);
        atomicAdd(&g_deg[c.x], w.x);
        atomicAdd(&g_deg[c.y], w.y);
        atomicAdd(&g_deg[c.z], w.z);
        atomicAdd(&g_deg[c.w], w.w);
    }
    if (i == 0) {
        for (int j = e4 * 4; j < e; j++) atomicAdd(&g_deg[col[j]], ew[j]);
    }
}

// dinv = rsqrt(deg); premultiply x_pre = dinv * x
__global__ void k_dinv(int n) {
    int i = blockIdx.x * blockDim.x + threadIdx.x;
    if (i < n) {
        float d = g_deg[i];
        float di = d > 0.f ? rsqrtf(d) : 0.f;
        g_dinv[i] = di;
        float4 x = g_x[i];
        x.x *= di; x.y *= di; x.z *= di;
        g_x[i] = x;
    }
}

// re-zero deg for next call AND pull home/away streams into L2 (side stream, under k_msg)
__global__ void k_zeropre(int n, const int4* __restrict__ home4,
                          const int4* __restrict__ away4, int b4) {
    int i = blockIdx.x * blockDim.x + threadIdx.x;
    if (i < n) g_deg[i] = 0.f;
    // touch index streams so they are L2-resident when k_mlp runs
    int acc = 0;
    for (int j = i; j < b4; j += gridDim.x * blockDim.x) {
        int4 h = __ldg(&home4[j]);
        int4 a = __ldg(&away4[j]);
        acc += h.x + h.y + h.z + h.w + a.x + a.y + a.z + a.w;
    }
    // block-level sink write (deterministic, never read)
    if (threadIdx.x == 0 && blockIdx.x < 2048) g_sink[blockIdx.x] = acc;
}

// agg[col] += ew * x_pre[row]   (2 random sectors per edge: gather + v4 red)
__global__ void k_msg(const int4* __restrict__ row4, const int4* __restrict__ col4,
                      const float4* __restrict__ ew4, int e4,
                      const int* __restrict__ row, const int* __restrict__ col,
                      const float* __restrict__ ew, int e) {
    int i = blockIdx.x * blockDim.x + threadIdx.x;
    if (i < e4) {
        int4   r = __ldg(&row4[i]);
        int4   c = __ldg(&col4[i]);
        float4 w = __ldg(&ew4[i]);
        float4 x0 = g_x[r.x];
        float4 x1 = g_x[r.y];
        float4 x2 = g_x[r.z];
        float4 x3 = g_x[r.w];
        red_v4(reinterpret_cast<float*>(&g_agg[c.x]), w.x * x0.x, w.x * x0.y, w.x * x0.z);
        red_v4(reinterpret_cast<float*>(&g_agg[c.y]), w.y * x1.x, w.y * x1.y, w.y * x1.z);
        red_v4(reinterpret_cast<float*>(&g_agg[c.z]), w.z * x2.x, w.z * x2.y, w.z * x2.z);
        red_v4(reinterpret_cast<float*>(&g_agg[c.w]), w.w * x3.x, w.w * x3.y, w.w * x3.z);
    }
    if (i == 0) {
        for (int j = e4 * 4; j < e; j++) {
            float4 xv = g_x[row[j]];
            float  w  = ew[j];
            red_v4(reinterpret_cast<float*>(&g_agg[col[j]]), w * xv.x, w * xv.y, w * xv.z);
        }
    }
}

// conv1 output: x = leaky_relu(dinv[c]*agg[c] + b_conv)
__global__ void k_node(int n) {
    int i = blockIdx.x * blockDim.x + threadIdx.x;
    if (i < n) {
        float4 a = g_agg[i];
        float  di = g_dinv[i];
        float4 o;
        o.x = lrelu(di * a.x + g_w[9]);
        o.y = lrelu(di * a.y + g_w[10]);
        o.z = lrelu(di * a.z + g_w[11]);
        o.w = 0.f;
        g_x[i] = o;
    }
}

// MLP per batch element; emits out + per-block (max, sum exp(o - max)) partials
// 8 items/thread; int4 index loads, float4 output stores
#define MLP_ITEMS 8
__global__ void k_mlp(const int4* __restrict__ home4, const int4* __restrict__ away4,
                      float4* __restrict__ out4, int b) {
    __shared__ float w[80];
    if (threadIdx.x < 80) w[threadIdx.x] = g_w[threadIdx.x];
    __syncthreads();

    int tid  = blockIdx.x * blockDim.x + threadIdx.x;
    int base = tid * MLP_ITEMS;            // item index; base*3 divisible by 4
    float o[MLP_ITEMS][3];
    int   nval = 0;
    float m0 = -INFINITY, m1 = -INFINITY, m2 = -INFINITY;

    if (base + MLP_ITEMS <= b) {
        int4 h0 = __ldg(&home4[tid * 2]);
        int4 h1 = __ldg(&home4[tid * 2 + 1]);
        int4 a0 = __ldg(&away4[tid * 2]);
        int4 a1 = __ldg(&away4[tid * 2 + 1]);
        int hi[8] = {h0.x, h0.y, h0.z, h0.w, h1.x, h1.y, h1.z, h1.w};
        int ai[8] = {a0.x, a0.y, a0.z, a0.w, a1.x, a1.y, a1.z, a1.w};
        #pragma unroll
        for (int t = 0; t < MLP_ITEMS; t++) {
            float4 xh = g_x[hi[t]];
            float4 xa = g_x[ai[t]];
            float h[6] = {xh.x, xh.y, xh.z, xa.x, xa.y, xa.z};
            float u[6];
            #pragma unroll
            for (int j = 0; j < 6; j++) {
                float s = w[48 + j];
                #pragma unroll
                for (int i2 = 0; i2 < 6; i2++) s += h[i2] * w[12 + i2 * 6 + j];
                u[j] = lrelu(s);
            }
            #pragma unroll
            for (int j = 0; j < 3; j++) {
                float s = w[72 + j];
                #pragma unroll
                for (int i2 = 0; i2 < 6; i2++) s += u[i2] * w[54 + i2 * 3 + j];
                o[t][j] = lrelu(s);
            }
            m0 = fmaxf(m0, o[t][0]);
            m1 = fmaxf(m1, o[t][1]);
            m2 = fmaxf(m2, o[t][2]);
        }
        nval = MLP_ITEMS;
        // 24 contiguous floats -> 6 float4 stores
        const float* of = &o[0][0];
        int vbase = (base * 3) / 4;
        #pragma unroll
        for (int v = 0; v < 6; v++)
            out4[vbase + v] = make_float4(of[4 * v], of[4 * v + 1], of[4 * v + 2], of[4 * v + 3]);
    } else {
        // tail: scalar path
        const int* home = (const int*)home4;
        const int* away = (const int*)away4;
        float* out = (float*)out4;
        #pragma unroll
        for (int t = 0; t < MLP_ITEMS; t++) {
            int idx = base + t;
            if (idx < b) {
                float4 xh = g_x[__ldg(&home[idx])];
                float4 xa = g_x[__ldg(&away[idx])];
                float h[6] = {xh.x, xh.y, xh.z, xa.x, xa.y, xa.z};
                float u[6];
                #pragma unroll
                for (int j = 0; j < 6; j++) {
                    float s = w[48 + j];
                    #pragma unroll
                    for (int i2 = 0; i2 < 6; i2++) s += h[i2] * w[12 + i2 * 6 + j];
                    u[j] = lrelu(s);
                }
                #pragma unroll
                for (int j = 0; j < 3; j++) {
                    float s = w[72 + j];
                    #pragma unroll
                    for (int i2 = 0; i2 < 6; i2++) s += u[i2] * w[54 + i2 * 3 + j];
                    o[t][j] = lrelu(s);
                }
                out[3 * idx + 0] = o[t][0];
                out[3 * idx + 1] = o[t][1];
                out[3 * idx + 2] = o[t][2];
                m0 = fmaxf(m0, o[t][0]);
                m1 = fmaxf(m1, o[t][1]);
                m2 = fmaxf(m2, o[t][2]);
                nval = t + 1;
            }
        }
    }

    // block max reduction
    #pragma unroll
    for (int off = 16; off; off >>= 1) {
        m0 = fmaxf(m0, __shfl_xor_sync(0xFFFFFFFFu, m0, off));
        m1 = fmaxf(m1, __shfl_xor_sync(0xFFFFFFFFu, m1, off));
        m2 = fmaxf(m2, __shfl_xor_sync(0xFFFFFFFFu, m2, off));
    }
    __shared__ float sm[3][8];
    int lane = threadIdx.x & 31, wpw = threadIdx.x >> 5;
    if (lane == 0) { sm[0][wpw] = m0; sm[1][wpw] = m1; sm[2][wpw] = m2; }
    __syncthreads();
    float M0 = sm[0][0], M1 = sm[1][0], M2 = sm[2][0];
    #pragma unroll
    for (int k = 1; k < 8; k++) {
        M0 = fmaxf(M0, sm[0][k]); M1 = fmaxf(M1, sm[1][k]); M2 = fmaxf(M2, sm[2][k]);
    }
    // block sums of exp(o - blockmax) from registers
    float s0 = 0.f, s1 = 0.f, s2 = 0.f;
    #pragma unroll
    for (int t = 0; t < MLP_ITEMS; t++) {
        if (t < nval) {
            s0 += __expf(o[t][0] - M0);
            s1 += __expf(o[t][1] - M1);
            s2 += __expf(o[t][2] - M2);
        }
    }
    #pragma unroll
    for (int off = 16; off; off >>= 1) {
        s0 += __shfl_xor_sync(0xFFFFFFFFu, s0, off);
        s1 += __shfl_xor_sync(0xFFFFFFFFu, s1, off);
        s2 += __shfl_xor_sync(0xFFFFFFFFu, s2, off);
    }
    __syncthreads();
    if (lane == 0) { sm[0][wpw] = s0; sm[1][wpw] = s1; sm[2][wpw] = s2; }
    __syncthreads();
    if (threadIdx.x == 0) {
        float t0 = 0.f, t1 = 0.f, t2 = 0.f;
        #pragma unroll
        for (int k = 0; k < 8; k++) { t0 += sm[0][k]; t1 += sm[1][k]; t2 += sm[2][k]; }
        int bb = blockIdx.x;
        g_pmax[0 * PART_MAX + bb] = M0;
        g_pmax[1 * PART_MAX + bb] = M1;
        g_pmax[2 * PART_MAX + bb] = M2;
        g_psum[0 * PART_MAX + bb] = t0;
        g_psum[1 * PART_MAX + bb] = t1;
        g_psum[2 * PART_MAX + bb] = t2;
    }
}

// merge per-block partials -> lse per column (single block, all 3 channels in one sweep)
__global__ void k_merge(int nb) {
    __shared__ float smx[3][32];
    __shared__ float sms[3][32];
    __shared__ float sM[3];
    int t = threadIdx.x;          // 1024 threads
    int lane = t & 31, wpw = t >> 5;
    float m[3], s[3];
    #pragma unroll
    for (int c = 0; c < 3; c++) {
        m[c] = (t < nb) ? g_pmax[c * PART_MAX + t] : -INFINITY;
        s[c] = (t < nb) ? g_psum[c * PART_MAX + t] : 0.f;
    }
    #pragma unroll
    for (int c = 0; c < 3; c++) {
        float mw = m[c];
        #pragma unroll
        for (int off = 16; off; off >>= 1) mw = fmaxf(mw, __shfl_xor_sync(0xFFFFFFFFu, mw, off));
        if (lane == 0) smx[c][wpw] = mw;
    }
    __syncthreads();
    if (t < 3) {
        float M = smx[t][0];
        #pragma unroll
        for (int k = 1; k < 32; k++) M = fmaxf(M, smx[t][k]);
        sM[t] = M;
    }
    __syncthreads();
    #pragma unroll
    for (int c = 0; c < 3; c++) {
        float sv = s[c] * __expf(m[c] - sM[c]);
        #pragma unroll
        for (int off = 16; off; off >>= 1) sv += __shfl_xor_sync(0xFFFFFFFFu, sv, off);
        if (lane == 0) sms[c][wpw] = sv;
    }
    __syncthreads();
    if (t < 3) {
        float S = 0.f;
        #pragma unroll
        for (int k = 0; k < 32; k++) S += sms[t][k];
        g_lse[t] = sM[t] + logf(S);
    }
}

// out -= lse[col]; 8 elems/thread (2x float4) + scalar tail
__global__ void k_final(float4* __restrict__ out4, int nvec2, float* __restrict__ out, int total) {
    float l0 = g_lse[0], l1 = g_lse[1], l2 = g_lse[2];
    int v = blockIdx.x * blockDim.x + threadIdx.x;   // pair index
    if (v < nvec2) {
        float4 oa = out4[2 * v];
        float4 ob = out4[2 * v + 1];
        int m = (v * 8) % 3;           // channel of first element
        float A, Bc, C;
        if (m == 0)      { A = l0; Bc = l1; C = l2; }
        else if (m == 1) { A = l1; Bc = l2; C = l0; }
        else             { A = l2; Bc = l0; C = l1; }
        oa.x -= A;  oa.y -= Bc; oa.z -= C;  oa.w -= A;
        ob.x -= Bc; ob.y -= C;  ob.z -= A;  ob.w -= Bc;
        out4[2 * v]     = oa;
        out4[2 * v + 1] = ob;
    }
    if (v == 0) {
        for (int j = nvec2 * 8; j < total; j++) out[j] -= g_lse[j % 3];
    }
}

// ---------------- launch ----------------
extern "C" void kernel_launch(void* const* d_in, const int* in_sizes, int n_in,
                              void* d_out, int out_size) {
    const int*   edge_index = (const int*)d_in[0];   // [2, E]
    const float* ew         = (const float*)d_in[1]; // [E]
    const int*   home       = (const int*)d_in[2];   // [B]
    const int*   away       = (const int*)d_in[3];   // [B]
    const float* emb        = (const float*)d_in[4]; // [N, 3]
    float*       out        = (float*)d_out;         // [B, 3]

    const int E = in_sizes[1];
    const int B = in_sizes[2];
    int       N = in_sizes[4] / 3;
    if (N > N_MAX) N = N_MAX;

    const int* row = edge_index;
    const int* col = edge_index + E;
    const int  E4  = E / 4;
    const int  B4  = B / 4;

    cudaStream_t s1;
    cudaStreamCreateWithFlags(&s1, cudaStreamNonBlocking);
    cudaEvent_t eFork, eJoin, eFork2, eJoin2;
    cudaEventCreateWithFlags(&eFork, cudaEventDisableTiming);
    cudaEventCreateWithFlags(&eJoin, cudaEventDisableTiming);
    cudaEventCreateWithFlags(&eFork2, cudaEventDisableTiming);
    cudaEventCreateWithFlags(&eJoin2, cudaEventDisableTiming);

    const int T = 256;

    // fork immediately: side does weights + x/agg init while main does deg atomics
    cudaEventRecord(eFork, 0);
    cudaStreamWaitEvent(s1, eFork, 0);
    k_weights<<<1, 64, 0, s1>>>((const float*)d_in[5], (const float*)d_in[6],
                                (const float*)d_in[7], (const float*)d_in[8],
                                (const float*)d_in[9], (const float*)d_in[10]);
    k_initx<<<(N + T - 1) / T, T, 0, s1>>>(emb, N);
    cudaEventRecord(eJoin, s1);

    // main: deg atomics start at t=0 (g_deg==0 invariant)
    k_deg<<<(E4 + T - 1) / T, T>>>((const int4*)col, (const float4*)ew, E4, col, ew, E);

    cudaStreamWaitEvent(0, eJoin, 0);   // join side work

    k_dinv<<<(N + T - 1) / T, T>>>(N);

    // side: re-zero deg + prefetch home/away into L2, overlapped under k_msg
    cudaEventRecord(eFork2, 0);
    cudaStreamWaitEvent(s1, eFork2, 0);
    k_zeropre<<<(N + T - 1) / T, T, 0, s1>>>(N, (const int4*)home, (const int4*)away, B4);
    cudaEventRecord(eJoin2, s1);

    k_msg<<<(E4 + T - 1) / T, T>>>((const int4*)row, (const int4*)col,
                                   (const float4*)ew, E4, row, col, ew, E);
    k_node<<<(N + T - 1) / T, T>>>(N);

    cudaStreamWaitEvent(0, eJoin2, 0);  // join prefetch/zero before MLP

    const int items_per_block = T * MLP_ITEMS;
    const int nb = (B + items_per_block - 1) / items_per_block;
    k_mlp<<<nb, T>>>((const int4*)home, (const int4*)away, (float4*)out, B);
    k_merge<<<1, 1024>>>(nb);

    const int total = 3 * B;
    const int nvec2 = total / 8;
    k_final<<<(nvec2 + T - 1) / T, T>>>((float4*)out, nvec2, out, total);
}

// round 12
// speedup vs baseline: 1.0412x; 1.0163x over previous
#include <cuda_runtime.h>
#include <math.h>

#define N_MAX 1000000
#define PART_MAX 4096

// ---------------- device scratch (no allocation allowed) ----------------
static __device__ float    g_deg[N_MAX];     // weighted in-degree (zero at entry, re-zeroed post-use)
static __device__ float4   g_x[N_MAX];       // x=emb@w_conv -> premult dinv*x
static __device__ float4   g_agg[N_MAX];     // message accumulator; .w carries dinv[node]
static __device__ float    g_pmax[3 * PART_MAX]; // per-block column max
static __device__ float    g_psum[3 * PART_MAX]; // per-block sum exp(o - blockmax)
static __device__ float    g_lse[3];         // final logsumexp per column
static __device__ int      g_sink[2048];     // prefetch sink (never read)

// packed weights: [0:9) w_conv, [9:12) b_conv, [12:48) w1, [48:54) b1,
//                 [54:72) w3, [72:75) b3
static __device__ float g_w[80];

__device__ __forceinline__ float lrelu(float x) { return x >= 0.f ? x : 0.01f * x; }

__device__ __forceinline__ void red_v4(float* p, float a, float b, float c) {
    asm volatile("red.global.add.v4.f32 [%0], {%1, %2, %3, %4};"
                 :: "l"(p), "f"(a), "f"(b), "f"(c), "f"(0.f) : "memory");
}

// ---------------- kernels ----------------

__global__ void k_weights(const float* __restrict__ wconv, const float* __restrict__ bconv,
                          const float* __restrict__ w1, const float* __restrict__ b1,
                          const float* __restrict__ w3, const float* __restrict__ b3) {
    int t = threadIdx.x;
    if (t < 9)  g_w[t]      = wconv[t];
    if (t < 3)  g_w[9 + t]  = bconv[t];
    if (t < 36) g_w[12 + t] = w1[t];
    if (t < 6)  g_w[48 + t] = b1[t];
    if (t < 18) g_w[54 + t] = w3[t];
    if (t < 3)  g_w[72 + t] = b3[t];
}

// x = emb @ w_conv; zero agg   (side stream, overlaps k_deg)
__global__ void k_initx(const float* __restrict__ emb, int n) {
    int i = blockIdx.x * blockDim.x + threadIdx.x;
    if (i < n) {
        float e0 = emb[3 * i + 0];
        float e1 = emb[3 * i + 1];
        float e2 = emb[3 * i + 2];
        float4 x;
        x.x = e0 * g_w[0] + e1 * g_w[3] + e2 * g_w[6];
        x.y = e0 * g_w[1] + e1 * g_w[4] + e2 * g_w[7];
        x.z = e0 * g_w[2] + e1 * g_w[5] + e2 * g_w[8];
        x.w = 0.f;
        g_x[i] = x;
        g_agg[i] = make_float4(0.f, 0.f, 0.f, 0.f);
    }
}

// weighted in-degree over target nodes (col); 4 edges per thread
// PRECONDITION: g_deg == 0 (BSS-zero on first call; k_zeropre restores per call)
__global__ void k_deg(const int4* __restrict__ col4, const float4* __restrict__ ew4,
                      int e4, const int* __restrict__ col, const float* __restrict__ ew, int e) {
    int i = blockIdx.x * blockDim.x + threadIdx.x;
    if (i < e4) {
        int4   c = __ldg(&col4[i]);
        float4 w = __ldg(&ew4[i]);
        atomicAdd(&g_deg[c.x], w.x);
        atomicAdd(&g_deg[c.y], w.y);
        atomicAdd(&g_deg[c.z], w.z);
        atomicAdd(&g_deg[c.w], w.w);
    }
    if (i == 0) {
        for (int j = e4 * 4; j < e; j++) atomicAdd(&g_deg[col[j]], ew[j]);
    }
}

// dinv = rsqrt(deg); x_pre = dinv * x; stash dinv in g_agg[i].w
// (v4 RED in k_msg adds 0.f to .w, so dinv survives aggregation)
__global__ void k_dinv(int n) {
    int i = blockIdx.x * blockDim.x + threadIdx.x;
    if (i < n) {
        float d = g_deg[i];
        float di = d > 0.f ? rsqrtf(d) : 0.f;
        float4 x = g_x[i];
        x.x *= di; x.y *= di; x.z *= di;
        g_x[i] = x;
        g_agg[i].w = di;
    }
}

// re-zero deg for next call AND pull home/away streams into L2 (side stream, under k_msg)
__global__ void k_zeropre(int n, const int4* __restrict__ home4,
                          const int4* __restrict__ away4, int b4) {
    int i = blockIdx.x * blockDim.x + threadIdx.x;
    if (i < n) g_deg[i] = 0.f;
    int acc = 0;
    for (int j = i; j < b4; j += gridDim.x * blockDim.x) {
        int4 h = __ldg(&home4[j]);
        int4 a = __ldg(&away4[j]);
        acc += h.x + h.y + h.z + h.w + a.x + a.y + a.z + a.w;
    }
    if (threadIdx.x == 0 && blockIdx.x < 2048) g_sink[blockIdx.x] = acc;
}

// agg[col].xyz += ew * x_pre[row]   (.w += 0 -> dinv preserved)
__global__ void k_msg(const int4* __restrict__ row4, const int4* __restrict__ col4,
                      const float4* __restrict__ ew4, int e4,
                      const int* __restrict__ row, const int* __restrict__ col,
                      const float* __restrict__ ew, int e) {
    int i = blockIdx.x * blockDim.x + threadIdx.x;
    if (i < e4) {
        int4   r = __ldg(&row4[i]);
        int4   c = __ldg(&col4[i]);
        float4 w = __ldg(&ew4[i]);
        float4 x0 = g_x[r.x];
        float4 x1 = g_x[r.y];
        float4 x2 = g_x[r.z];
        float4 x3 = g_x[r.w];
        red_v4(reinterpret_cast<float*>(&g_agg[c.x]), w.x * x0.x, w.x * x0.y, w.x * x0.z);
        red_v4(reinterpret_cast<float*>(&g_agg[c.y]), w.y * x1.x, w.y * x1.y, w.y * x1.z);
        red_v4(reinterpret_cast<float*>(&g_agg[c.z]), w.z * x2.x, w.z * x2.y, w.z * x2.z);
        red_v4(reinterpret_cast<float*>(&g_agg[c.w]), w.w * x3.x, w.w * x3.y, w.w * x3.z);
    }
    if (i == 0) {
        for (int j = e4 * 4; j < e; j++) {
            float4 xv = g_x[row[j]];
            float  w  = ew[j];
            red_v4(reinterpret_cast<float*>(&g_agg[col[j]]), w * xv.x, w * xv.y, w * xv.z);
        }
    }
}

// conv1 output computed inline from one agg gather: lrelu(agg.w * agg.xyz + b_conv)
__device__ __forceinline__ void node_feat(const float* w, int idx, float* h) {
    float4 a = g_agg[idx];
    h[0] = lrelu(a.w * a.x + w[9]);
    h[1] = lrelu(a.w * a.y + w[10]);
    h[2] = lrelu(a.w * a.z + w[11]);
}

// MLP per batch element (conv epilogue fused into the gather);
// emits out + per-block (max, sum exp(o - max)) partials
#define MLP_ITEMS 8
__global__ void k_mlp(const int4* __restrict__ home4, const int4* __restrict__ away4,
                      float4* __restrict__ out4, int b) {
    __shared__ float w[80];
    if (threadIdx.x < 80) w[threadIdx.x] = g_w[threadIdx.x];
    __syncthreads();

    int tid  = blockIdx.x * blockDim.x + threadIdx.x;
    int base = tid * MLP_ITEMS;            // item index; base*3 divisible by 4
    float o[MLP_ITEMS][3];
    int   nval = 0;
    float m0 = -INFINITY, m1 = -INFINITY, m2 = -INFINITY;

    if (base + MLP_ITEMS <= b) {
        int4 h0 = __ldg(&home4[tid * 2]);
        int4 h1 = __ldg(&home4[tid * 2 + 1]);
        int4 a0 = __ldg(&away4[tid * 2]);
        int4 a1 = __ldg(&away4[tid * 2 + 1]);
        int hi[8] = {h0.x, h0.y, h0.z, h0.w, h1.x, h1.y, h1.z, h1.w};
        int ai[8] = {a0.x, a0.y, a0.z, a0.w, a1.x, a1.y, a1.z, a1.w};
        #pragma unroll
        for (int t = 0; t < MLP_ITEMS; t++) {
            float h[6];
            node_feat(w, hi[t], h);
            node_feat(w, ai[t], h + 3);
            float u[6];
            #pragma unroll
            for (int j = 0; j < 6; j++) {
                float s = w[48 + j];
                #pragma unroll
                for (int i2 = 0; i2 < 6; i2++) s += h[i2] * w[12 + i2 * 6 + j];
                u[j] = lrelu(s);
            }
            #pragma unroll
            for (int j = 0; j < 3; j++) {
                float s = w[72 + j];
                #pragma unroll
                for (int i2 = 0; i2 < 6; i2++) s += u[i2] * w[54 + i2 * 3 + j];
                o[t][j] = lrelu(s);
            }
            m0 = fmaxf(m0, o[t][0]);
            m1 = fmaxf(m1, o[t][1]);
            m2 = fmaxf(m2, o[t][2]);
        }
        nval = MLP_ITEMS;
        // 24 contiguous floats -> 6 float4 stores
        const float* of = &o[0][0];
        int vbase = (base * 3) / 4;
        #pragma unroll
        for (int v = 0; v < 6; v++)
            out4[vbase + v] = make_float4(of[4 * v], of[4 * v + 1], of[4 * v + 2], of[4 * v + 3]);
    } else {
        // tail: scalar path
        const int* home = (const int*)home4;
        const int* away = (const int*)away4;
        float* out = (float*)out4;
        #pragma unroll
        for (int t = 0; t < MLP_ITEMS; t++) {
            int idx = base + t;
            if (idx < b) {
                float h[6];
                node_feat(w, __ldg(&home[idx]), h);
                node_feat(w, __ldg(&away[idx]), h + 3);
                float u[6];
                #pragma unroll
                for (int j = 0; j < 6; j++) {
                    float s = w[48 + j];
                    #pragma unroll
                    for (int i2 = 0; i2 < 6; i2++) s += h[i2] * w[12 + i2 * 6 + j];
                    u[j] = lrelu(s);
                }
                #pragma unroll
                for (int j = 0; j < 3; j++) {
                    float s = w[72 + j];
                    #pragma unroll
                    for (int i2 = 0; i2 < 6; i2++) s += u[i2] * w[54 + i2 * 3 + j];
                    o[t][j] = lrelu(s);
                }
                out[3 * idx + 0] = o[t][0];
                out[3 * idx + 1] = o[t][1];
                out[3 * idx + 2] = o[t][2];
                m0 = fmaxf(m0, o[t][0]);
                m1 = fmaxf(m1, o[t][1]);
                m2 = fmaxf(m2, o[t][2]);
                nval = t + 1;
            }
        }
    }

    // block max reduction
    #pragma unroll
    for (int off = 16; off; off >>= 1) {
        m0 = fmaxf(m0, __shfl_xor_sync(0xFFFFFFFFu, m0, off));
        m1 = fmaxf(m1, __shfl_xor_sync(0xFFFFFFFFu, m1, off));
        m2 = fmaxf(m2, __shfl_xor_sync(0xFFFFFFFFu, m2, off));
    }
    __shared__ float sm[3][8];
    int lane = threadIdx.x & 31, wpw = threadIdx.x >> 5;
    if (lane == 0) { sm[0][wpw] = m0; sm[1][wpw] = m1; sm[2][wpw] = m2; }
    __syncthreads();
    float M0 = sm[0][0], M1 = sm[1][0], M2 = sm[2][0];
    #pragma unroll
    for (int k = 1; k < 8; k++) {
        M0 = fmaxf(M0, sm[0][k]); M1 = fmaxf(M1, sm[1][k]); M2 = fmaxf(M2, sm[2][k]);
    }
    // block sums of exp(o - blockmax) from registers
    float s0 = 0.f, s1 = 0.f, s2 = 0.f;
    #pragma unroll
    for (int t = 0; t < MLP_ITEMS; t++) {
        if (t < nval) {
            s0 += __expf(o[t][0] - M0);
            s1 += __expf(o[t][1] - M1);
            s2 += __expf(o[t][2] - M2);
        }
    }
    #pragma unroll
    for (int off = 16; off; off >>= 1) {
        s0 += __shfl_xor_sync(0xFFFFFFFFu, s0, off);
        s1 += __shfl_xor_sync(0xFFFFFFFFu, s1, off);
        s2 += __shfl_xor_sync(0xFFFFFFFFu, s2, off);
    }
    __syncthreads();
    if (lane == 0) { sm[0][wpw] = s0; sm[1][wpw] = s1; sm[2][wpw] = s2; }
    __syncthreads();
    if (threadIdx.x == 0) {
        float t0 = 0.f, t1 = 0.f, t2 = 0.f;
        #pragma unroll
        for (int k = 0; k < 8; k++) { t0 += sm[0][k]; t1 += sm[1][k]; t2 += sm[2][k]; }
        int bb = blockIdx.x;
        g_pmax[0 * PART_MAX + bb] = M0;
        g_pmax[1 * PART_MAX + bb] = M1;
        g_pmax[2 * PART_MAX + bb] = M2;
        g_psum[0 * PART_MAX + bb] = t0;
        g_psum[1 * PART_MAX + bb] = t1;
        g_psum[2 * PART_MAX + bb] = t2;
    }
}

// merge per-block partials -> lse per column (single block, all 3 channels in one sweep)
__global__ void k_merge(int nb) {
    __shared__ float smx[3][32];
    __shared__ float sms[3][32];
    __shared__ float sM[3];
    int t = threadIdx.x;          // 1024 threads
    int lane = t & 31, wpw = t >> 5;
    float m[3], s[3];
    #pragma unroll
    for (int c = 0; c < 3; c++) {
        m[c] = (t < nb) ? g_pmax[c * PART_MAX + t] : -INFINITY;
        s[c] = (t < nb) ? g_psum[c * PART_MAX + t] : 0.f;
    }
    #pragma unroll
    for (int c = 0; c < 3; c++) {
        float mw = m[c];
        #pragma unroll
        for (int off = 16; off; off >>= 1) mw = fmaxf(mw, __shfl_xor_sync(0xFFFFFFFFu, mw, off));
        if (lane == 0) smx[c][wpw] = mw;
    }
    __syncthreads();
    if (t < 3) {
        float M = smx[t][0];
        #pragma unroll
        for (int k = 1; k < 32; k++) M = fmaxf(M, smx[t][k]);
        sM[t] = M;
    }
    __syncthreads();
    #pragma unroll
    for (int c = 0; c < 3; c++) {
        float sv = s[c] * __expf(m[c] - sM[c]);
        #pragma unroll
        for (int off = 16; off; off >>= 1) sv += __shfl_xor_sync(0xFFFFFFFFu, sv, off);
        if (lane == 0) sms[c][wpw] = sv;
    }
    __syncthreads();
    if (t < 3) {
        float S = 0.f;
        #pragma unroll
        for (int k = 0; k < 32; k++) S += sms[t][k];
        g_lse[t] = sM[t] + logf(S);
    }
}

// out -= lse[col]; 8 elems/thread (2x float4) + scalar tail
__global__ void k_final(float4* __restrict__ out4, int nvec2, float* __restrict__ out, int total) {
    float l0 = g_lse[0], l1 = g_lse[1], l2 = g_lse[2];
    int v = blockIdx.x * blockDim.x + threadIdx.x;   // pair index
    if (v < nvec2) {
        float4 oa = out4[2 * v];
        float4 ob = out4[2 * v + 1];
        int m = (v * 8) % 3;           // channel of first element
        float A, Bc, C;
        if (m == 0)      { A = l0; Bc = l1; C = l2; }
        else if (m == 1) { A = l1; Bc = l2; C = l0; }
        else             { A = l2; Bc = l0; C = l1; }
        oa.x -= A;  oa.y -= Bc; oa.z -= C;  oa.w -= A;
        ob.x -= Bc; ob.y -= C;  ob.z -= A;  ob.w -= Bc;
        out4[2 * v]     = oa;
        out4[2 * v + 1] = ob;
    }
    if (v == 0) {
        for (int j = nvec2 * 8; j < total; j++) out[j] -= g_lse[j % 3];
    }
}

// ---------------- launch ----------------
extern "C" void kernel_launch(void* const* d_in, const int* in_sizes, int n_in,
                              void* d_out, int out_size) {
    const int*   edge_index = (const int*)d_in[0];   // [2, E]
    const float* ew         = (const float*)d_in[1]; // [E]
    const int*   home       = (const int*)d_in[2];   // [B]
    const int*   away       = (const int*)d_in[3];   // [B]
    const float* emb        = (const float*)d_in[4]; // [N, 3]
    float*       out        = (float*)d_out;         // [B, 3]

    const int E = in_sizes[1];
    const int B = in_sizes[2];
    int       N = in_sizes[4] / 3;
    if (N > N_MAX) N = N_MAX;

    const int* row = edge_index;
    const int* col = edge_index + E;
    const int  E4  = E / 4;
    const int  B4  = B / 4;

    cudaStream_t s1;
    cudaStreamCreateWithFlags(&s1, cudaStreamNonBlocking);
    cudaEvent_t eFork, eJoin, eFork2, eJoin2;
    cudaEventCreateWithFlags(&eFork, cudaEventDisableTiming);
    cudaEventCreateWithFlags(&eJoin, cudaEventDisableTiming);
    cudaEventCreateWithFlags(&eFork2, cudaEventDisableTiming);
    cudaEventCreateWithFlags(&eJoin2, cudaEventDisableTiming);

    const int T = 256;

    // fork immediately: side does weights + x/agg init while main does deg atomics
    cudaEventRecord(eFork, 0);
    cudaStreamWaitEvent(s1, eFork, 0);
    k_weights<<<1, 64, 0, s1>>>((const float*)d_in[5], (const float*)d_in[6],
                                (const float*)d_in[7], (const float*)d_in[8],
                                (const float*)d_in[9], (const float*)d_in[10]);
    k_initx<<<(N + T - 1) / T, T, 0, s1>>>(emb, N);
    cudaEventRecord(eJoin, s1);

    // main: deg atomics start at t=0 (g_deg==0 invariant)
    k_deg<<<(E4 + T - 1) / T, T>>>((const int4*)col, (const float4*)ew, E4, col, ew, E);

    cudaStreamWaitEvent(0, eJoin, 0);   // join side work

    k_dinv<<<(N + T - 1) / T, T>>>(N);

    // side: re-zero deg + prefetch home/away into L2, overlapped under k_msg
    cudaEventRecord(eFork2, 0);
    cudaStreamWaitEvent(s1, eFork2, 0);
    k_zeropre<<<(N + T - 1) / T, T, 0, s1>>>(N, (const int4*)home, (const int4*)away, B4);
    cudaEventRecord(eJoin2, s1);

    k_msg<<<(E4 + T - 1) / T, T>>>((const int4*)row, (const int4*)col,
                                   (const float4*)ew, E4, row, col, ew, E);

    cudaStreamWaitEvent(0, eJoin2, 0);  // join prefetch/zero before MLP

    const int items_per_block = T * MLP_ITEMS;
    const int nb = (B + items_per_block - 1) / items_per_block;
    k_mlp<<<nb, T>>>((const int4*)home, (const int4*)away, (float4*)out, B);
    k_merge<<<1, 1024>>>(nb);

    const int total = 3 * B;
    const int nvec2 = total / 8;
    k_final<<<(nvec2 + T - 1) / T, T>>>((float4*)out, nvec2, out, total);
}

// round 15
// speedup vs baseline: 1.0413x; 1.0001x over previous
#include <cuda_runtime.h>
#include <math.h>

#define N_MAX 1000000
#define PART_MAX 4096

// ---------------- device scratch (no allocation allowed) ----------------
static __device__ float    g_deg[N_MAX];     // weighted in-degree (zero at entry, re-zeroed post-use)
static __device__ float4   g_x[N_MAX];       // .xyz = emb@w_conv ; .w = dinv[node]
static __device__ float4   g_agg[N_MAX];     // message accumulator; .w carries dinv[node]
static __device__ float    g_pmax[3 * PART_MAX]; // per-block column max
static __device__ float    g_psum[3 * PART_MAX]; // per-block sum exp(o - blockmax)
static __device__ float    g_lse[3];         // final logsumexp per column
static __device__ int      g_sink[2048];     // prefetch sink (never read)

// packed weights: [0:9) w_conv, [9:12) b_conv, [12:48) w1, [48:54) b1,
//                 [54:72) w3, [72:75) b3
static __device__ float g_w[80];

__device__ __forceinline__ float lrelu(float x) { return x >= 0.f ? x : 0.01f * x; }

__device__ __forceinline__ void red_v4(float* p, float a, float b, float c) {
    asm volatile("red.global.add.v4.f32 [%0], {%1, %2, %3, %4};"
                 :: "l"(p), "f"(a), "f"(b), "f"(c), "f"(0.f) : "memory");
}

// ---------------- kernels ----------------

__global__ void k_weights(const float* __restrict__ wconv, const float* __restrict__ bconv,
                          const float* __restrict__ w1, const float* __restrict__ b1,
                          const float* __restrict__ w3, const float* __restrict__ b3) {
    int t = threadIdx.x;
    if (t < 9)  g_w[t]      = wconv[t];
    if (t < 3)  g_w[9 + t]  = bconv[t];
    if (t < 36) g_w[12 + t] = w1[t];
    if (t < 6)  g_w[48 + t] = b1[t];
    if (t < 18) g_w[54 + t] = w3[t];
    if (t < 3)  g_w[72 + t] = b3[t];
}

// x = emb @ w_conv; zero agg   (side stream, overlaps k_deg)
__global__ void k_initx(const float* __restrict__ emb, int n) {
    int i = blockIdx.x * blockDim.x + threadIdx.x;
    if (i < n) {
        float e0 = emb[3 * i + 0];
        float e1 = emb[3 * i + 1];
        float e2 = emb[3 * i + 2];
        float4 x;
        x.x = e0 * g_w[0] + e1 * g_w[3] + e2 * g_w[6];
        x.y = e0 * g_w[1] + e1 * g_w[4] + e2 * g_w[7];
        x.z = e0 * g_w[2] + e1 * g_w[5] + e2 * g_w[8];
        x.w = 0.f;
        g_x[i] = x;
        g_agg[i] = make_float4(0.f, 0.f, 0.f, 0.f);
    }
}

// weighted in-degree over target nodes (col); 4 edges per thread
// PRECONDITION: g_deg == 0 (BSS-zero on first call; k_zeropre restores per call)
__global__ void k_deg(const int4* __restrict__ col4, const float4* __restrict__ ew4,
                      int e4, const int* __restrict__ col, const float* __restrict__ ew, int e) {
    int i = blockIdx.x * blockDim.x + threadIdx.x;
    if (i < e4) {
        int4   c = __ldg(&col4[i]);
        float4 w = __ldg(&ew4[i]);
        atomicAdd(&g_deg[c.x], w.x);
        atomicAdd(&g_deg[c.y], w.y);
        atomicAdd(&g_deg[c.z], w.z);
        atomicAdd(&g_deg[c.w], w.w);
    }
    if (i == 0) {
        for (int j = e4 * 4; j < e; j++) atomicAdd(&g_deg[col[j]], ew[j]);
    }
}

// dinv = rsqrt(deg); stash into g_x[i].w (applied per-edge in k_msg) and
// g_agg[i].w (applied in the MLP epilogue). No x read-modify-write.
__global__ void k_dinv(int n) {
    int i = blockIdx.x * blockDim.x + threadIdx.x;
    if (i < n) {
        float d = g_deg[i];
        float di = d > 0.f ? rsqrtf(d) : 0.f;
        g_x[i].w   = di;
        g_agg[i].w = di;
    }
}

// re-zero deg for next call AND pull home/away streams into L2 (side stream, under k_msg)
__global__ void k_zeropre(int n, const int4* __restrict__ home4,
                          const int4* __restrict__ away4, int b4) {
    int i = blockIdx.x * blockDim.x + threadIdx.x;
    if (i < n) g_deg[i] = 0.f;
    int acc = 0;
    for (int j = i; j < b4; j += gridDim.x * blockDim.x) {
        int4 h = __ldg(&home4[j]);
        int4 a = __ldg(&away4[j]);
        acc += h.x + h.y + h.z + h.w + a.x + a.y + a.z + a.w;
    }
    if (threadIdx.x == 0 && blockIdx.x < 2048) g_sink[blockIdx.x] = acc;
}

// agg[col].xyz += (ew * dinv[row]) * x[row]   (.w += 0 -> dinv preserved)
// dinv[row] rides in the gathered float4's .w — zero extra sectors.
__global__ void k_msg(const int4* __restrict__ row4, const int4* __restrict__ col4,
                      const float4* __restrict__ ew4, int e4,
                      const int* __restrict__ row, const int* __restrict__ col,
                      const float* __restrict__ ew, int e) {
    int i = blockIdx.x * blockDim.x + threadIdx.x;
    if (i < e4) {
        int4   r = __ldg(&row4[i]);
        int4   c = __ldg(&col4[i]);
        float4 w = __ldg(&ew4[i]);
        float4 x0 = g_x[r.x];
        float4 x1 = g_x[r.y];
        float4 x2 = g_x[r.z];
        float4 x3 = g_x[r.w];
        float n0 = w.x * x0.w;
        float n1 = w.y * x1.w;
        float n2 = w.z * x2.w;
        float n3 = w.w * x3.w;
        red_v4(reinterpret_cast<float*>(&g_agg[c.x]), n0 * x0.x, n0 * x0.y, n0 * x0.z);
        red_v4(reinterpret_cast<float*>(&g_agg[c.y]), n1 * x1.x, n1 * x1.y, n1 * x1.z);
        red_v4(reinterpret_cast<float*>(&g_agg[c.z]), n2 * x2.x, n2 * x2.y, n2 * x2.z);
        red_v4(reinterpret_cast<float*>(&g_agg[c.w]), n3 * x3.x, n3 * x3.y, n3 * x3.z);
    }
    if (i == 0) {
        for (int j = e4 * 4; j < e; j++) {
            float4 xv = g_x[row[j]];
            float  nw = ew[j] * xv.w;
            red_v4(reinterpret_cast<float*>(&g_agg[col[j]]), nw * xv.x, nw * xv.y, nw * xv.z);
        }
    }
}

// conv1 output computed inline from one agg gather: lrelu(agg.w * agg.xyz + b_conv)
__device__ __forceinline__ void node_feat(const float* w, int idx, float* h) {
    float4 a = g_agg[idx];
    h[0] = lrelu(a.w * a.x + w[9]);
    h[1] = lrelu(a.w * a.y + w[10]);
    h[2] = lrelu(a.w * a.z + w[11]);
}

// MLP per batch element (conv epilogue fused into the gather);
// emits out + per-block (max, sum exp(o - max)) partials
#define MLP_ITEMS 8
__global__ void k_mlp(const int4* __restrict__ home4, const int4* __restrict__ away4,
                      float4* __restrict__ out4, int b) {
    __shared__ float w[80];
    if (threadIdx.x < 80) w[threadIdx.x] = g_w[threadIdx.x];
    __syncthreads();

    int tid  = blockIdx.x * blockDim.x + threadIdx.x;
    int base = tid * MLP_ITEMS;            // item index; base*3 divisible by 4
    float o[MLP_ITEMS][3];
    int   nval = 0;
    float m0 = -INFINITY, m1 = -INFINITY, m2 = -INFINITY;

    if (base + MLP_ITEMS <= b) {
        int4 h0 = __ldg(&home4[tid * 2]);
        int4 h1 = __ldg(&home4[tid * 2 + 1]);
        int4 a0 = __ldg(&away4[tid * 2]);
        int4 a1 = __ldg(&away4[tid * 2 + 1]);
        int hi[8] = {h0.x, h0.y, h0.z, h0.w, h1.x, h1.y, h1.z, h1.w};
        int ai[8] = {a0.x, a0.y, a0.z, a0.w, a1.x, a1.y, a1.z, a1.w};
        #pragma unroll
        for (int t = 0; t < MLP_ITEMS; t++) {
            float h[6];
            node_feat(w, hi[t], h);
            node_feat(w, ai[t], h + 3);
            float u[6];
            #pragma unroll
            for (int j = 0; j < 6; j++) {
                float s = w[48 + j];
                #pragma unroll
                for (int i2 = 0; i2 < 6; i2++) s += h[i2] * w[12 + i2 * 6 + j];
                u[j] = lrelu(s);
            }
            #pragma unroll
            for (int j = 0; j < 3; j++) {
                float s = w[72 + j];
                #pragma unroll
                for (int i2 = 0; i2 < 6; i2++) s += u[i2] * w[54 + i2 * 3 + j];
                o[t][j] = lrelu(s);
            }
            m0 = fmaxf(m0, o[t][0]);
            m1 = fmaxf(m1, o[t][1]);
            m2 = fmaxf(m2, o[t][2]);
        }
        nval = MLP_ITEMS;
        // 24 contiguous floats -> 6 float4 stores
        const float* of = &o[0][0];
        int vbase = (base * 3) / 4;
        #pragma unroll
        for (int v = 0; v < 6; v++)
            out4[vbase + v] = make_float4(of[4 * v], of[4 * v + 1], of[4 * v + 2], of[4 * v + 3]);
    } else {
        // tail: scalar path
        const int* home = (const int*)home4;
        const int* away = (const int*)away4;
        float* out = (float*)out4;
        #pragma unroll
        for (int t = 0; t < MLP_ITEMS; t++) {
            int idx = base + t;
            if (idx < b) {
                float h[6];
                node_feat(w, __ldg(&home[idx]), h);
                node_feat(w, __ldg(&away[idx]), h + 3);
                float u[6];
                #pragma unroll
                for (int j = 0; j < 6; j++) {
                    float s = w[48 + j];
                    #pragma unroll
                    for (int i2 = 0; i2 < 6; i2++) s += h[i2] * w[12 + i2 * 6 + j];
                    u[j] = lrelu(s);
                }
                #pragma unroll
                for (int j = 0; j < 3; j++) {
                    float s = w[72 + j];
                    #pragma unroll
                    for (int i2 = 0; i2 < 6; i2++) s += u[i2] * w[54 + i2 * 3 + j];
                    o[t][j] = lrelu(s);
                }
                out[3 * idx + 0] = o[t][0];
                out[3 * idx + 1] = o[t][1];
                out[3 * idx + 2] = o[t][2];
                m0 = fmaxf(m0, o[t][0]);
                m1 = fmaxf(m1, o[t][1]);
                m2 = fmaxf(m2, o[t][2]);
                nval = t + 1;
            }
        }
    }

    // block max reduction
    #pragma unroll
    for (int off = 16; off; off >>= 1) {
        m0 = fmaxf(m0, __shfl_xor_sync(0xFFFFFFFFu, m0, off));
        m1 = fmaxf(m1, __shfl_xor_sync(0xFFFFFFFFu, m1, off));
        m2 = fmaxf(m2, __shfl_xor_sync(0xFFFFFFFFu, m2, off));
    }
    __shared__ float sm[3][8];
    int lane = threadIdx.x & 31, wpw = threadIdx.x >> 5;
    if (lane == 0) { sm[0][wpw] = m0; sm[1][wpw] = m1; sm[2][wpw] = m2; }
    __syncthreads();
    float M0 = sm[0][0], M1 = sm[1][0], M2 = sm[2][0];
    #pragma unroll
    for (int k = 1; k < 8; k++) {
        M0 = fmaxf(M0, sm[0][k]); M1 = fmaxf(M1, sm[1][k]); M2 = fmaxf(M2, sm[2][k]);
    }
    // block sums of exp(o - blockmax) from registers
    float s0 = 0.f, s1 = 0.f, s2 = 0.f;
    #pragma unroll
    for (int t = 0; t < MLP_ITEMS; t++) {
        if (t < nval) {
            s0 += __expf(o[t][0] - M0);
            s1 += __expf(o[t][1] - M1);
            s2 += __expf(o[t][2] - M2);
        }
    }
    #pragma unroll
    for (int off = 16; off; off >>= 1) {
        s0 += __shfl_xor_sync(0xFFFFFFFFu, s0, off);
        s1 += __shfl_xor_sync(0xFFFFFFFFu, s1, off);
        s2 += __shfl_xor_sync(0xFFFFFFFFu, s2, off);
    }
    __syncthreads();
    if (lane == 0) { sm[0][wpw] = s0; sm[1][wpw] = s1; sm[2][wpw] = s2; }
    __syncthreads();
    if (threadIdx.x == 0) {
        float t0 = 0.f, t1 = 0.f, t2 = 0.f;
        #pragma unroll
        for (int k = 0; k < 8; k++) { t0 += sm[0][k]; t1 += sm[1][k]; t2 += sm[2][k]; }
        int bb = blockIdx.x;
        g_pmax[0 * PART_MAX + bb] = M0;
        g_pmax[1 * PART_MAX + bb] = M1;
        g_pmax[2 * PART_MAX + bb] = M2;
        g_psum[0 * PART_MAX + bb] = t0;
        g_psum[1 * PART_MAX + bb] = t1;
        g_psum[2 * PART_MAX + bb] = t2;
    }
}

// merge per-block partials -> lse per column (single block, all 3 channels in one sweep)
__global__ void k_merge(int nb) {
    __shared__ float smx[3][32];
    __shared__ float sms[3][32];
    __shared__ float sM[3];
    int t = threadIdx.x;          // 1024 threads
    int lane = t & 31, wpw = t >> 5;
    float m[3], s[3];
    #pragma unroll
    for (int c = 0; c < 3; c++) {
        m[c] = (t < nb) ? g_pmax[c * PART_MAX + t] : -INFINITY;
        s[c] = (t < nb) ? g_psum[c * PART_MAX + t] : 0.f;
    }
    #pragma unroll
    for (int c = 0; c < 3; c++) {
        float mw = m[c];
        #pragma unroll
        for (int off = 16; off; off >>= 1) mw = fmaxf(mw, __shfl_xor_sync(0xFFFFFFFFu, mw, off));
        if (lane == 0) smx[c][wpw] = mw;
    }
    __syncthreads();
    if (t < 3) {
        float M = smx[t][0];
        #pragma unroll
        for (int k = 1; k < 32; k++) M = fmaxf(M, smx[t][k]);
        sM[t] = M;
    }
    __syncthreads();
    #pragma unroll
    for (int c = 0; c < 3; c++) {
        float sv = s[c] * __expf(m[c] - sM[c]);
        #pragma unroll
        for (int off = 16; off; off >>= 1) sv += __shfl_xor_sync(0xFFFFFFFFu, sv, off);
        if (lane == 0) sms[c][wpw] = sv;
    }
    __syncthreads();
    if (t < 3) {
        float S = 0.f;
        #pragma unroll
        for (int k = 0; k < 32; k++) S += sms[t][k];
        g_lse[t] = sM[t] + logf(S);
    }
}

// out -= lse[col]; 8 elems/thread (2x float4) + scalar tail
__global__ void k_final(float4* __restrict__ out4, int nvec2, float* __restrict__ out, int total) {
    float l0 = g_lse[0], l1 = g_lse[1], l2 = g_lse[2];
    int v = blockIdx.x * blockDim.x + threadIdx.x;   // pair index
    if (v < nvec2) {
        float4 oa = out4[2 * v];
        float4 ob = out4[2 * v + 1];
        int m = (v * 8) % 3;           // channel of first element
        float A, Bc, C;
        if (m == 0)      { A = l0; Bc = l1; C = l2; }
        else if (m == 1) { A = l1; Bc = l2; C = l0; }
        else             { A = l2; Bc = l0; C = l1; }
        oa.x -= A;  oa.y -= Bc; oa.z -= C;  oa.w -= A;
        ob.x -= Bc; ob.y -= C;  ob.z -= A;  ob.w -= Bc;
        out4[2 * v]     = oa;
        out4[2 * v + 1] = ob;
    }
    if (v == 0) {
        for (int j = nvec2 * 8; j < total; j++) out[j] -= g_lse[j % 3];
    }
}

// ---------------- launch ----------------
extern "C" void kernel_launch(void* const* d_in, const int* in_sizes, int n_in,
                              void* d_out, int out_size) {
    const int*   edge_index = (const int*)d_in[0];   // [2, E]
    const float* ew         = (const float*)d_in[1]; // [E]
    const int*   home       = (const int*)d_in[2];   // [B]
    const int*   away       = (const int*)d_in[3];   // [B]
    const float* emb        = (const float*)d_in[4]; // [N, 3]
    float*       out        = (float*)d_out;         // [B, 3]

    const int E = in_sizes[1];
    const int B = in_sizes[2];
    int       N = in_sizes[4] / 3;
    if (N > N_MAX) N = N_MAX;

    const int* row = edge_index;
    const int* col = edge_index + E;
    const int  E4  = E / 4;
    const int  B4  = B / 4;

    cudaStream_t s1;
    cudaStreamCreateWithFlags(&s1, cudaStreamNonBlocking);
    cudaEvent_t eFork, eJoin, eFork2, eJoin2;
    cudaEventCreateWithFlags(&eFork, cudaEventDisableTiming);
    cudaEventCreateWithFlags(&eJoin, cudaEventDisableTiming);
    cudaEventCreateWithFlags(&eFork2, cudaEventDisableTiming);
    cudaEventCreateWithFlags(&eJoin2, cudaEventDisableTiming);

    const int T = 256;

    // fork immediately: side does weights + x/agg init while main does deg atomics
    cudaEventRecord(eFork, 0);
    cudaStreamWaitEvent(s1, eFork, 0);
    k_weights<<<1, 64, 0, s1>>>((const float*)d_in[5], (const float*)d_in[6],
                                (const float*)d_in[7], (const float*)d_in[8],
                                (const float*)d_in[9], (const float*)d_in[10]);
    k_initx<<<(N + T - 1) / T, T, 0, s1>>>(emb, N);
    cudaEventRecord(eJoin, s1);

    // main: deg atomics start at t=0 (g_deg==0 invariant)
    k_deg<<<(E4 + T - 1) / T, T>>>((const int4*)col, (const float4*)ew, E4, col, ew, E);

    cudaStreamWaitEvent(0, eJoin, 0);   // join side work

    k_dinv<<<(N + T - 1) / T, T>>>(N);

    // side: re-zero deg + prefetch home/away into L2, overlapped under k_msg
    cudaEventRecord(eFork2, 0);
    cudaStreamWaitEvent(s1, eFork2, 0);
    k_zeropre<<<(N + T - 1) / T, T, 0, s1>>>(N, (const int4*)home, (const int4*)away, B4);
    cudaEventRecord(eJoin2, s1);

    k_msg<<<(E4 + T - 1) / T, T>>>((const int4*)row, (const int4*)col,
                                   (const float4*)ew, E4, row, col, ew, E);

    cudaStreamWaitEvent(0, eJoin2, 0);  // join prefetch/zero before MLP

    const int items_per_block = T * MLP_ITEMS;
    const int nb = (B + items_per_block - 1) / items_per_block;
    k_mlp<<<nb, T>>>((const int4*)home, (const int4*)away, (float4*)out, B);
    k_merge<<<1, 1024>>>(nb);

    const int total = 3 * B;
    const int nvec2 = total / 8;
    k_final<<<(nvec2 + T - 1) / T, T>>>((float4*)out, nvec2, out, total);
}